// round 7
// baseline (speedup 1.0000x reference)
#include <cuda_runtime.h>
#include <cuda_bf16.h>
#include <math.h>
#include <stdint.h>

#define NN 4096
#define EE 32768
#define BB 64
#define GG 10
#define ZWP 4224      // padded z row stride (66*64); real cols = 4160, bias slice at 4096
#define NC 4160

__device__ float g_out[NN*64];
__device__ float g_h[NN*64];
__device__ float g_hidden[EE*64];
__device__ float g_z[(size_t)NN*ZWP];
__device__ float g_agg[NN*64];
__device__ float g_m[NN*64];
__device__ float g_m2[NN*64];
__device__ float g_s[NN*GG];
__device__ float g_inv[GG*64];
__device__ float g_shift[GG*64];
__device__ float g_gi[NN*192];
__device__ float g_gh[NN*192];
__device__ float g_pooled[BB*64];
__device__ int   g_cntd[NN];
__device__ int   g_cnts[NN];
__device__ int   g_bcnt[BB];
__device__ int   g_soff[NN+1];
__device__ int   g_cur[NN];
__device__ int   g_order[EE];
__device__ __nv_bfloat16 g_Ah[NN*64];
__device__ __nv_bfloat16 g_Al[NN*64];
__device__ __nv_bfloat16 g_Bh[3*4224*64];
__device__ __nv_bfloat16 g_Bl[3*4224*64];

__device__ __forceinline__ uint32_t smem_u32(const void* p) {
    uint32_t a;
    asm("{ .reg .u64 t; cvta.to.shared.u64 t, %1; cvt.u32.u64 %0, t; }" : "=r"(a) : "l"(p));
    return a;
}
__device__ __forceinline__ void ldm_x4(uint32_t* r, uint32_t addr) {
    asm volatile("ldmatrix.sync.aligned.m8n8.x4.shared.b16 {%0,%1,%2,%3}, [%4];"
                 : "=r"(r[0]), "=r"(r[1]), "=r"(r[2]), "=r"(r[3]) : "r"(addr));
}
__device__ __forceinline__ void mma16816(float* d, const uint32_t* a, uint32_t b0, uint32_t b1) {
    asm volatile(
        "mma.sync.aligned.m16n8k16.row.col.f32.bf16.bf16.f32 "
        "{%0,%1,%2,%3}, {%4,%5,%6,%7}, {%8,%9}, {%0,%1,%2,%3};"
        : "+f"(d[0]), "+f"(d[1]), "+f"(d[2]), "+f"(d[3])
        : "r"(a[0]), "r"(a[1]), "r"(a[2]), "r"(a[3]), "r"(b0), "r"(b1));
}

// ---------- bf16 split conversions ----------
__global__ void conv_out(const float* __restrict__ out,
                         __nv_bfloat16* __restrict__ Ah, __nv_bfloat16* __restrict__ Al)
{
    int i = blockIdx.x * 256 + threadIdx.x;
    float v = out[i];
    __nv_bfloat16 hi = __float2bfloat16(v);
    Ah[i] = hi;
    Al[i] = __float2bfloat16(v - __bfloat162float(hi));
}

// B[l][c][f]: c<4096: w2[l][t=c>>6][f*64 + (c&63)]; 4096<=c<4160: b2[l][f*64 + c-4096]; else 0
__global__ void conv_w2(const float* __restrict__ w2, const float* __restrict__ b2,
                        __nv_bfloat16* __restrict__ Bh, __nv_bfloat16* __restrict__ Bl)
{
    int i = blockIdx.x * 256 + threadIdx.x;       // 3*4224*64
    int f = i & 63;
    int c = (i >> 6) % 4224;
    int l = i / (4224 * 64);
    float v = 0.f;
    if (c < 4096) {
        int t = c >> 6, o = c & 63;
        v = w2[(size_t)l*262144 + t*4096 + f*64 + o];
    } else if (c < NC) {
        v = b2[(size_t)l*4096 + f*64 + (c - 4096)];
    }
    __nv_bfloat16 hi = __float2bfloat16(v);
    Bh[i] = hi;
    Bl[i] = __float2bfloat16(v - __bfloat162float(hi));
}

// ---------- tensor-core z GEMM via mma.sync: CTA tile 128x128, K=64, hi/lo 3-pass ----------
// A: [4096][64] bf16 row-major (k contig). B: [4224][64] bf16 "n-major" (k contig) == col-major kxn.
__global__ void zgemm_mma(const __nv_bfloat16* __restrict__ Ah, const __nv_bfloat16* __restrict__ Al,
                          const __nv_bfloat16* __restrict__ Bh, const __nv_bfloat16* __restrict__ Bl,
                          float* __restrict__ z)
{
    extern __shared__ char smem[];
    const int SA_H = 0, SA_L = 16384, SB_H = 32768, SB_L = 49152;
    const uint32_t sb = smem_u32(smem);
    const int tid = threadIdx.x;           // 256
    const int wid = tid >> 5, lane = tid & 31;

    const int n0 = blockIdx.x * 128;       // M offset
    const int c0 = blockIdx.y * 128;       // N offset

    // stage tiles (128 rows x 128B each), 16B-chunk XOR swizzle: chunk^(row&7)
    const uint4* gAh = (const uint4*)(Ah + (size_t)n0 * 64);
    const uint4* gAl = (const uint4*)(Al + (size_t)n0 * 64);
    const uint4* gBh = (const uint4*)(Bh + (size_t)c0 * 64);
    const uint4* gBl = (const uint4*)(Bl + (size_t)c0 * 64);
    for (int idx = tid; idx < 1024; idx += 256) {
        int row = idx >> 3, ch = idx & 7;
        uint32_t off = row * 128 + ((ch ^ (row & 7)) << 4);
        *(uint4*)(smem + SA_H + off) = gAh[idx];
        *(uint4*)(smem + SA_L + off) = gAl[idx];
        *(uint4*)(smem + SB_H + off) = gBh[idx];
        *(uint4*)(smem + SB_L + off) = gBl[idx];
    }
    __syncthreads();

    const int wm = (wid & 3) * 32;     // warp M offset (rows)
    const int wn = (wid >> 2) * 64;    // warp N offset (cols)
    float d[2][8][4];
#pragma unroll
    for (int mi = 0; mi < 2; mi++)
#pragma unroll
        for (int ni = 0; ni < 8; ni++)
#pragma unroll
            for (int q = 0; q < 4; q++) d[mi][ni][q] = 0.f;

    const int lrow = lane & 15, lhalf = lane >> 4;
#pragma unroll
    for (int pass = 0; pass < 3; pass++) {
        const int aoff = (pass == 2) ? SA_L : SA_H;
        const int boff = (pass == 1) ? SB_L : SB_H;
#pragma unroll
        for (int ks = 0; ks < 4; ks++) {
            const int chunk = 2 * ks + lhalf;
            uint32_t a[2][4];
#pragma unroll
            for (int mi = 0; mi < 2; mi++) {
                int row = wm + mi * 16 + lrow;
                ldm_x4(a[mi], sb + aoff + row * 128 + (((chunk ^ (row & 7))) << 4));
            }
            uint32_t b[4][4];
#pragma unroll
            for (int nj = 0; nj < 4; nj++) {
                int row = wn + nj * 16 + lrow;
                ldm_x4(b[nj], sb + boff + row * 128 + (((chunk ^ (row & 7))) << 4));
            }
#pragma unroll
            for (int mi = 0; mi < 2; mi++)
#pragma unroll
                for (int nj = 0; nj < 4; nj++) {
                    mma16816(d[mi][2*nj],     a[mi], b[nj][0], b[nj][2]);
                    mma16816(d[mi][2*nj + 1], a[mi], b[nj][1], b[nj][3]);
                }
        }
    }

    // epilogue: direct stores to z
    const int gid = lane >> 2, t4 = lane & 3;
#pragma unroll
    for (int mi = 0; mi < 2; mi++) {
        int rbase = n0 + wm + mi * 16 + gid;
#pragma unroll
        for (int ni = 0; ni < 8; ni++) {
            int c = c0 + wn + ni * 8 + t4 * 2;
            *(float2*)&z[(size_t)rbase * ZWP + c]       = make_float2(d[mi][ni][0], d[mi][ni][1]);
            *(float2*)&z[(size_t)(rbase + 8) * ZWP + c] = make_float2(d[mi][ni][2], d[mi][ni][3]);
        }
    }
}

// ================= SIMT kernels (unchanged from 677us version) =================
template<int K, int J, int TC, bool BT, bool RELU, bool HASBASE, bool DUAL>
__global__ void gemm_small(const float* __restrict__ A, const float* __restrict__ B,
                           const float* __restrict__ bias,
                           const float* __restrict__ base, const int* __restrict__ cnt,
                           float* __restrict__ C, float* __restrict__ C2)
{
    constexpr int KC = 32;
    constexpr int CG = J / TC;
    constexpr int RG = 256 / CG;
    constexpr int TR = 64 / RG;
    static_assert(RG * CG == 256, "");
    __shared__ float As[KC][68];
    __shared__ float Bs[KC][J];
    __shared__ float bsh[J];
    const int tid = threadIdx.x;
    const int n0 = blockIdx.x * 64;
    const int rg = tid / CG, cg = tid % CG;
    float acc[TR][TC];
#pragma unroll
    for (int i = 0; i < TR; i++)
#pragma unroll
        for (int j = 0; j < TC; j++) acc[i][j] = 0.f;
    for (int j = tid; j < J; j += 256) bsh[j] = bias[j];

    for (int kc = 0; kc < K; kc += KC) {
        __syncthreads();
        for (int idx = tid; idx < 64*KC; idx += 256) {
            int k = idx % KC, r = idx / KC;
            As[k][r] = A[(size_t)(n0 + r) * K + kc + k];
        }
        if (!BT) {
            for (int idx = tid; idx < KC*J; idx += 256) {
                int k = idx / J, j = idx % J;
                Bs[k][j] = B[(kc + k) * J + j];
            }
        } else {
            for (int idx = tid; idx < KC*J; idx += 256) {
                int j = idx / KC, k = idx % KC;
                Bs[k][j] = B[j * K + kc + k];
            }
        }
        __syncthreads();
#pragma unroll 8
        for (int k = 0; k < KC; k++) {
            float a[TR], b[TC];
#pragma unroll
            for (int i = 0; i < TR; i++) a[i] = As[k][rg*TR + i];
#pragma unroll
            for (int j = 0; j < TC; j++) b[j] = Bs[k][cg*TC + j];
#pragma unroll
            for (int i = 0; i < TR; i++)
#pragma unroll
                for (int j = 0; j < TC; j++)
                    acc[i][j] = fmaf(a[i], b[j], acc[i][j]);
        }
    }
#pragma unroll
    for (int i = 0; i < TR; i++) {
        int r = n0 + rg*TR + i;
        float rs = HASBASE ? (1.f / (float)max(cnt[r], 1)) : 0.f;
#pragma unroll
        for (int j = 0; j < TC; j++) {
            int col = cg*TC + j;
            float v = acc[i][j] + bsh[col];
            if (HASBASE) v += rs * base[(size_t)r*J + col];
            if (RELU) v = fmaxf(v, 0.f);
            C[(size_t)r*J + col] = v;
            if (DUAL) C2[(size_t)r*J + col] = v;
        }
    }
}

__global__ void counts(const int* __restrict__ ei, const int* __restrict__ batch,
                       int* __restrict__ cntd, int* __restrict__ cnts, int* __restrict__ bcnt)
{
    int e = blockIdx.x * 256 + threadIdx.x;
    if (e < EE) {
        atomicAdd(&cnts[ei[e]], 1);
        atomicAdd(&cntd[ei[EE + e]], 1);
    }
    if (e < NN) atomicAdd(&bcnt[batch[e]], 1);
}

__global__ void scan_src(const int* __restrict__ cnt, int* __restrict__ off, int* __restrict__ cur)
{
    __shared__ int part[1024];
    const int t = threadIdx.x;
    int c[4]; int s = 0;
#pragma unroll
    for (int i = 0; i < 4; i++) { c[i] = cnt[t*4 + i]; s += c[i]; }
    part[t] = s;
    __syncthreads();
    for (int st = 1; st < 1024; st <<= 1) {
        int v = (t >= st) ? part[t - st] : 0;
        __syncthreads();
        part[t] += v;
        __syncthreads();
    }
    int base = (t > 0) ? part[t - 1] : 0;
#pragma unroll
    for (int i = 0; i < 4; i++) { off[t*4 + i] = base; cur[t*4 + i] = base; base += c[i]; }
    if (t == 1023) off[NN] = part[1023];
}

__global__ void scatter_edges(const int* __restrict__ ei, int* __restrict__ cur,
                              int* __restrict__ order)
{
    int e = blockIdx.x * 256 + threadIdx.x;
    if (e < EE) {
        int p = atomicAdd(&cur[ei[e]], 1);
        order[p] = e;
    }
}

__global__ void edge_msg_csr(const float* __restrict__ hidden, const float* __restrict__ z,
                             const int* __restrict__ ei, const int* __restrict__ off,
                             const int* __restrict__ order, float* __restrict__ agg)
{
    const int s = blockIdx.x;
    const int beg = off[s], end = off[s + 1];
    if (beg == end) return;
    __shared__ float Zs[NC];
    __shared__ float hsh[8][64];
    const int t = threadIdx.x;
    const float4* zsrc = (const float4*)(z + (size_t)s * ZWP);
    for (int i = t; i < NC/4; i += 256) ((float4*)Zs)[i] = zsrc[i];
    __syncthreads();
    const int w = t >> 5, lane = t & 31;
    for (int idx = beg + w; idx < end; idx += 8) {
        const int e = order[idx];
        hsh[w][lane]      = hidden[(size_t)e*64 + lane];
        hsh[w][lane + 32] = hidden[(size_t)e*64 + 32 + lane];
        __syncwarp();
        float ax = Zs[4096 + 2*lane], ay = Zs[4096 + 2*lane + 1];
#pragma unroll 8
        for (int k = 0; k < 64; k++) {
            float h = hsh[w][k];
            float2 v = ((const float2*)Zs)[k*32 + lane];
            ax = fmaf(h, v.x, ax);
            ay = fmaf(h, v.y, ay);
        }
        const int dst = ei[EE + e];
        atomicAdd(&agg[(size_t)dst*64 + 2*lane],     ax);
        atomicAdd(&agg[(size_t)dst*64 + 2*lane + 1], ay);
        __syncwarp();
    }
}

__global__ void dgn_softmax(const float* __restrict__ m, const float* __restrict__ lin,
                            float* __restrict__ s)
{
    __shared__ float msh[64][65];
    __shared__ float lsh[64*GG];
    const int t = threadIdx.x;
    const int n0 = blockIdx.x * 64;
    for (int r = 0; r < 64; r++) msh[r][t] = m[(size_t)(n0 + r)*64 + t];
    for (int i = t; i < 64*GG; i += 64) lsh[i] = lin[i];
    __syncthreads();
    float logit[GG];
#pragma unroll
    for (int g = 0; g < GG; g++) logit[g] = 0.f;
    for (int k = 0; k < 64; k++) {
        float mv = msh[t][k];
#pragma unroll
        for (int g = 0; g < GG; g++) logit[g] = fmaf(mv, lsh[k*GG + g], logit[g]);
    }
    float mx = logit[0];
#pragma unroll
    for (int g = 1; g < GG; g++) mx = fmaxf(mx, logit[g]);
    float sum = 0.f;
#pragma unroll
    for (int g = 0; g < GG; g++) { logit[g] = expf(logit[g] - mx); sum += logit[g]; }
    float inv = 1.f / sum;
#pragma unroll
    for (int g = 0; g < GG; g++) s[(size_t)(n0 + t)*GG + g] = logit[g] * inv;
}

__global__ void dgn_stats(const float* __restrict__ m, const float* __restrict__ s,
                          const float* __restrict__ gamma, const float* __restrict__ beta,
                          float* __restrict__ inv, float* __restrict__ shift)
{
    const int c = blockIdx.x;
    const int g = c / 64, dd = c % 64;
    float sum = 0.f, sq = 0.f;
    for (int n = threadIdx.x; n < NN; n += 256) {
        float t = s[(size_t)n*GG + g] * m[(size_t)n*64 + dd];
        sum += t; sq = fmaf(t, t, sq);
    }
    __shared__ float rs[256], rq[256];
    rs[threadIdx.x] = sum; rq[threadIdx.x] = sq;
    __syncthreads();
    for (int st = 128; st > 0; st >>= 1) {
        if (threadIdx.x < st) { rs[threadIdx.x] += rs[threadIdx.x + st]; rq[threadIdx.x] += rq[threadIdx.x + st]; }
        __syncthreads();
    }
    if (threadIdx.x == 0) {
        float mu = rs[0] / (float)NN;
        float var = rq[0] / (float)NN - mu*mu;
        float iv = gamma[c] * rsqrtf(var + 1e-5f);
        inv[c] = iv;
        shift[c] = beta[c] - mu * iv;
    }
}

__global__ void dgn_apply(const float* __restrict__ m, const float* __restrict__ s,
                          const float* __restrict__ inv, const float* __restrict__ shift,
                          float* __restrict__ m2)
{
    __shared__ float ssh[64*GG];
    __shared__ float ish[GG*64];
    __shared__ float csh[64];
    const int t = threadIdx.x;
    const int n0 = blockIdx.x * 64;
    for (int i = t; i < 64*GG; i += 256) ssh[i] = s[(size_t)n0*GG + i];
    for (int i = t; i < GG*64; i += 256) ish[i] = inv[i];
    if (t < 64) {
        float cs = 0.f;
#pragma unroll
        for (int g = 0; g < GG; g++) cs += shift[g*64 + t];
        csh[t] = cs;
    }
    __syncthreads();
    for (int idx = t; idx < 4096; idx += 256) {
        int nl = idx / 64, dd = idx % 64;
        float a = 0.f;
#pragma unroll
        for (int g = 0; g < GG; g++) a = fmaf(ssh[nl*GG + g], ish[g*64 + dd], a);
        float mv = m[(size_t)(n0 + nl)*64 + dd];
        float v = mv + 0.01f * fmaf(mv, a, csh[dd]);
        m2[(size_t)(n0 + nl)*64 + dd] = fmaxf(v, 0.f);
    }
}

__global__ void gru_gate(const float* __restrict__ gi, const float* __restrict__ gh,
                         float* __restrict__ h, float* __restrict__ out)
{
    int i = blockIdx.x * 256 + threadIdx.x;
    int n = i >> 6, dd = i & 63;
    const float* gin = gi + (size_t)n*192;
    const float* ghn = gh + (size_t)n*192;
    float r  = 1.f / (1.f + expf(-(gin[dd] + ghn[dd])));
    float zz = 1.f / (1.f + expf(-(gin[64+dd] + ghn[64+dd])));
    float nn = tanhf(fmaf(r, ghn[128+dd], gin[128+dd]));
    float hv = h[i];
    float hnew = fmaf(zz, hv, (1.f - zz) * nn);
    h[i] = hnew;
    out[i] = hnew + out[i];
}

__global__ void pool(const float* __restrict__ out, const int* __restrict__ batch,
                     float* __restrict__ pooled)
{
    int i = blockIdx.x * 256 + threadIdx.x;
    atomicAdd(&pooled[batch[i >> 6]*64 + (i & 63)], out[i]);
}

__global__ void head(const float* __restrict__ pooled, const int* __restrict__ bcnt,
                     const float* __restrict__ postW, const float* __restrict__ postb,
                     const float* __restrict__ outW, const float* __restrict__ outb,
                     float* __restrict__ y)
{
    const int b = blockIdx.x;
    const int j = threadIdx.x;
    __shared__ float pr[64];
    __shared__ float red[64];
    float invv = 1.f / (float)max(bcnt[b], 1);
    pr[j] = pooled[b*64 + j] * invv;
    __syncthreads();
    float acc = postb[j];
    for (int k = 0; k < 64; k++) acc = fmaf(pr[k], postW[k*64 + j], acc);
    float pv = fmaxf(acc, 0.f) * outW[j];
    red[j] = pv;
    __syncthreads();
    for (int st = 32; st > 0; st >>= 1) {
        if (j < st) red[j] += red[j + st];
        __syncthreads();
    }
    if (j == 0) y[b] = red[0] + outb[0];
}

__global__ void tkl_kernel(const float* __restrict__ preW, const float* __restrict__ preb,
                           const float* __restrict__ postW, const float* __restrict__ postb,
                           const float* __restrict__ outW, const float* __restrict__ outb,
                           float* __restrict__ dst)
{
    const double logc = log(0.15 * sqrt(2.0 * 3.14159265358979323846));
    double acc = 0.0;
    const int tid = threadIdx.x;
    const float* arrs[6] = {preW, preb, postW, postb, outW, outb};
    const int lens[6] = {128*64, 64, 64*64, 64, 64, 1};
    for (int a = 0; a < 6; a++)
        for (int i = tid; i < lens[a]; i += 256) {
            double v = (double)arrs[a][i] / 0.15;
            acc += 0.5 * v * v + logc;
        }
    __shared__ double red[256];
    red[tid] = acc;
    __syncthreads();
    for (int st = 128; st > 0; st >>= 1) {
        if (tid < st) red[tid] += red[tid + st];
        __syncthreads();
    }
    if (tid == 0) dst[0] = (float)red[0];
}

extern "C" void kernel_launch(void* const* d_in, const int* in_sizes, int n_in,
                              void* d_out, int out_size)
{
    const float* x         = (const float*)d_in[0];
    const float* edge_attr = (const float*)d_in[1];
    const float* pre_W     = (const float*)d_in[2];
    const float* pre_b     = (const float*)d_in[3];
    const float* edge_w1   = (const float*)d_in[4];
    const float* edge_b1   = (const float*)d_in[5];
    const float* edge_w2   = (const float*)d_in[6];
    const float* edge_b2   = (const float*)d_in[7];
    const float* root_w    = (const float*)d_in[8];
    const float* root_b    = (const float*)d_in[9];
    const float* gru_wih   = (const float*)d_in[10];
    const float* gru_whh   = (const float*)d_in[11];
    const float* gru_bih   = (const float*)d_in[12];
    const float* gru_bhh   = (const float*)d_in[13];
    const float* gn_lin    = (const float*)d_in[14];
    const float* gn_gamma  = (const float*)d_in[15];
    const float* gn_beta   = (const float*)d_in[16];
    const float* post_W    = (const float*)d_in[17];
    const float* post_b    = (const float*)d_in[18];
    const float* out_W     = (const float*)d_in[19];
    const float* out_b     = (const float*)d_in[20];
    const int*   ei        = (const int*)d_in[21];
    const int*   batch     = (const int*)d_in[22];
    float* y = (float*)d_out;

    float *p_out, *p_h, *p_hidden, *p_z, *p_agg, *p_m, *p_m2, *p_s, *p_inv, *p_shift,
          *p_gi, *p_gh, *p_pooled;
    int *p_cntd, *p_cnts, *p_bcnt, *p_soff, *p_cur, *p_order;
    __nv_bfloat16 *p_Ah, *p_Al, *p_Bh, *p_Bl;
    cudaGetSymbolAddress((void**)&p_out, g_out);
    cudaGetSymbolAddress((void**)&p_h, g_h);
    cudaGetSymbolAddress((void**)&p_hidden, g_hidden);
    cudaGetSymbolAddress((void**)&p_z, g_z);
    cudaGetSymbolAddress((void**)&p_agg, g_agg);
    cudaGetSymbolAddress((void**)&p_m, g_m);
    cudaGetSymbolAddress((void**)&p_m2, g_m2);
    cudaGetSymbolAddress((void**)&p_s, g_s);
    cudaGetSymbolAddress((void**)&p_inv, g_inv);
    cudaGetSymbolAddress((void**)&p_shift, g_shift);
    cudaGetSymbolAddress((void**)&p_gi, g_gi);
    cudaGetSymbolAddress((void**)&p_gh, g_gh);
    cudaGetSymbolAddress((void**)&p_pooled, g_pooled);
    cudaGetSymbolAddress((void**)&p_cntd, g_cntd);
    cudaGetSymbolAddress((void**)&p_cnts, g_cnts);
    cudaGetSymbolAddress((void**)&p_bcnt, g_bcnt);
    cudaGetSymbolAddress((void**)&p_soff, g_soff);
    cudaGetSymbolAddress((void**)&p_cur, g_cur);
    cudaGetSymbolAddress((void**)&p_order, g_order);
    cudaGetSymbolAddress((void**)&p_Ah, g_Ah);
    cudaGetSymbolAddress((void**)&p_Al, g_Al);
    cudaGetSymbolAddress((void**)&p_Bh, g_Bh);
    cudaGetSymbolAddress((void**)&p_Bl, g_Bl);

    cudaFuncSetAttribute(zgemm_mma, cudaFuncAttributeMaxDynamicSharedMemorySize, 65536);

    cudaMemsetAsync(p_cntd, 0, NN * sizeof(int));
    cudaMemsetAsync(p_cnts, 0, NN * sizeof(int));
    cudaMemsetAsync(p_bcnt, 0, BB * sizeof(int));
    cudaMemsetAsync(p_pooled, 0, BB * 64 * sizeof(float));

    if (out_size >= 65)
        tkl_kernel<<<1, 256>>>(pre_W, pre_b, post_W, post_b, out_W, out_b, y + 64);

    counts<<<EE/256, 256>>>(ei, batch, p_cntd, p_cnts, p_bcnt);
    scan_src<<<1, 1024>>>(p_cnts, p_soff, p_cur);
    scatter_edges<<<EE/256, 256>>>(ei, p_cur, p_order);

    // W2 hi/lo split for all 3 layers
    conv_w2<<<3*4224*64/256, 256>>>(edge_w2, edge_b2, p_Bh, p_Bl);

    // pre FC + relu; writes both out and h
    gemm_small<128,64,4,false,true,false,true><<<NN/64, 256>>>(x, pre_W, pre_b, nullptr, nullptr, p_out, p_h);

    for (int i = 0; i < 3; i++) {
        const float* w1 = edge_w1 + (size_t)i*64*64;
        const float* b1 = edge_b1 + (size_t)i*64;

        gemm_small<64,64,4,false,true,false,false><<<EE/64, 256>>>(edge_attr, w1, b1, nullptr, nullptr, p_hidden, nullptr);

        conv_out<<<NN*64/256, 256>>>(p_out, p_Ah, p_Al);
        zgemm_mma<<<dim3(NN/128, 4224/128), 256, 65536>>>(
            p_Ah, p_Al, p_Bh + (size_t)i*4224*64, p_Bl + (size_t)i*4224*64, p_z);

        cudaMemsetAsync(p_agg, 0, NN*64*sizeof(float));
        edge_msg_csr<<<NN, 256>>>(p_hidden, p_z, ei, p_soff, p_order, p_agg);

        gemm_small<64,64,4,false,false,true,false><<<NN/64, 256>>>(p_out, root_w + (size_t)i*4096,
            root_b + (size_t)i*64, p_agg, p_cntd, p_m, nullptr);

        dgn_softmax<<<NN/64, 64>>>(p_m, gn_lin + (size_t)i*64*GG, p_s);
        dgn_stats<<<GG*64, 256>>>(p_m, p_s, gn_gamma + (size_t)i*GG*64, gn_beta + (size_t)i*GG*64, p_inv, p_shift);
        dgn_apply<<<NN/64, 256>>>(p_m, p_s, p_inv, p_shift, p_m2);

        gemm_small<64,192,12,true,false,false,false><<<NN/64, 256>>>(p_m2, gru_wih + (size_t)i*192*64,
            gru_bih + (size_t)i*192, nullptr, nullptr, p_gi, nullptr);
        gemm_small<64,192,12,true,false,false,false><<<NN/64, 256>>>(p_h, gru_whh + (size_t)i*192*64,
            gru_bhh + (size_t)i*192, nullptr, nullptr, p_gh, nullptr);
        gru_gate<<<NN*64/256, 256>>>(p_gi, p_gh, p_h, p_out);
    }

    pool<<<NN*64/256, 256>>>(p_out, batch, p_pooled);
    head<<<BB, 64>>>(p_pooled, p_bcnt, post_W, post_b, out_W, out_b, y);
}

// round 8
// speedup vs baseline: 1.4545x; 1.4545x over previous
#include <cuda_runtime.h>
#include <cuda_bf16.h>
#include <math.h>
#include <stdint.h>

#define NN 4096
#define EE 32768
#define BB 64
#define GG 10
#define ZWP 4224      // padded z row stride (66*64); real cols = 4160, bias slice at 4096
#define NC 4160

__device__ float g_out[NN*64];
__device__ float g_h[NN*64];
__device__ float g_hidden[EE*64];
__device__ float g_z[(size_t)NN*ZWP];
__device__ float g_agg[NN*64];
__device__ float g_m[NN*64];
__device__ float g_m2[NN*64];
__device__ float g_s[NN*GG];
__device__ float g_inv[GG*64];
__device__ float g_shift[GG*64];
__device__ float g_gi[NN*192];
__device__ float g_gh[NN*192];
__device__ float g_pooled[BB*64];
__device__ int   g_cntd[NN];
__device__ int   g_cnts[NN];
__device__ int   g_bcnt[BB];
__device__ int   g_soff[NN+1];
__device__ int   g_cur[NN];
__device__ int   g_order[EE];

// ---------- packed f32x2 helpers (Blackwell FFMA2 via PTX) ----------
__device__ __forceinline__ void fma2(uint64_t& d, uint64_t a, uint64_t b) {
    asm("fma.rn.f32x2 %0, %1, %2, %3;" : "=l"(d) : "l"(a), "l"(b), "l"(d));
}
__device__ __forceinline__ uint64_t splat2(float v) {
    uint64_t r;
    asm("mov.b64 %0, {%1, %1};" : "=l"(r) : "f"(v));
    return r;
}
__device__ __forceinline__ float2 u2f(uint64_t v) {
    float2 r;
    asm("mov.b64 {%0, %1}, %2;" : "=f"(r.x), "=f"(r.y) : "l"(v));
    return r;
}

// ---------- z GEMM: z[n, slice, :] = out[n,:] @ w2[slice] (slice 64 = b2), f32x2 inner ----------
// 128 threads; thread (rg,cg): rows rg*8..+7 (4 row-pairs), cols cg*4..+3.
__global__ void zgemm(const float* __restrict__ out, const float* __restrict__ w2,
                      const float* __restrict__ b2, float* __restrict__ z)
{
    __shared__ float As[64][68];     // As[k][r], rows contiguous -> row-pair LDS.64
    __shared__ float Bs[64][64];
    const int tid = threadIdx.x;     // 128
    const int n0 = blockIdx.x * 64;
    const int d  = blockIdx.y;
    const float* Bsrc = (d < 64) ? (w2 + d * 4096) : b2;
    for (int idx = tid; idx < 4096; idx += 128) {
        As[idx % 64][idx / 64] = out[(size_t)(n0 + idx / 64) * 64 + (idx % 64)];
        Bs[idx / 64][idx % 64] = Bsrc[idx];
    }
    __syncthreads();
    const int rg = tid >> 4, cg = tid & 15;    // rg 0..7, cg 0..15
    uint64_t acc[4][4];
#pragma unroll
    for (int p = 0; p < 4; p++)
#pragma unroll
        for (int j = 0; j < 4; j++) acc[p][j] = 0ull;
#pragma unroll 8
    for (int k = 0; k < 64; k++) {
        uint64_t a[4];
#pragma unroll
        for (int p = 0; p < 4; p++)
            a[p] = *(const uint64_t*)&As[k][rg*8 + 2*p];
#pragma unroll
        for (int j = 0; j < 4; j++) {
            uint64_t bs = splat2(Bs[k][cg*4 + j]);
#pragma unroll
            for (int p = 0; p < 4; p++) fma2(acc[p][j], a[p], bs);
        }
    }
#pragma unroll
    for (int p = 0; p < 4; p++) {
        float2 v0 = u2f(acc[p][0]), v1 = u2f(acc[p][1]), v2 = u2f(acc[p][2]), v3 = u2f(acc[p][3]);
        size_t r0 = (size_t)(n0 + rg*8 + 2*p) * ZWP + d*64 + cg*4;
        *(float4*)&z[r0]       = make_float4(v0.x, v1.x, v2.x, v3.x);
        *(float4*)&z[r0 + ZWP] = make_float4(v0.y, v1.y, v2.y, v3.y);
    }
}

// ================= SIMT kernels (identical to 677us version) =================
template<int K, int J, int TC, bool BT, bool RELU, bool HASBASE, bool DUAL>
__global__ void gemm_small(const float* __restrict__ A, const float* __restrict__ B,
                           const float* __restrict__ bias,
                           const float* __restrict__ base, const int* __restrict__ cnt,
                           float* __restrict__ C, float* __restrict__ C2)
{
    constexpr int KC = 32;
    constexpr int CG = J / TC;
    constexpr int RG = 256 / CG;
    constexpr int TR = 64 / RG;
    static_assert(RG * CG == 256, "");
    __shared__ float As[KC][68];
    __shared__ float Bs[KC][J];
    __shared__ float bsh[J];
    const int tid = threadIdx.x;
    const int n0 = blockIdx.x * 64;
    const int rg = tid / CG, cg = tid % CG;
    float acc[TR][TC];
#pragma unroll
    for (int i = 0; i < TR; i++)
#pragma unroll
        for (int j = 0; j < TC; j++) acc[i][j] = 0.f;
    for (int j = tid; j < J; j += 256) bsh[j] = bias[j];

    for (int kc = 0; kc < K; kc += KC) {
        __syncthreads();
        for (int idx = tid; idx < 64*KC; idx += 256) {
            int k = idx % KC, r = idx / KC;
            As[k][r] = A[(size_t)(n0 + r) * K + kc + k];
        }
        if (!BT) {
            for (int idx = tid; idx < KC*J; idx += 256) {
                int k = idx / J, j = idx % J;
                Bs[k][j] = B[(kc + k) * J + j];
            }
        } else {
            for (int idx = tid; idx < KC*J; idx += 256) {
                int j = idx / KC, k = idx % KC;
                Bs[k][j] = B[j * K + kc + k];
            }
        }
        __syncthreads();
#pragma unroll 8
        for (int k = 0; k < KC; k++) {
            float a[TR], b[TC];
#pragma unroll
            for (int i = 0; i < TR; i++) a[i] = As[k][rg*TR + i];
#pragma unroll
            for (int j = 0; j < TC; j++) b[j] = Bs[k][cg*TC + j];
#pragma unroll
            for (int i = 0; i < TR; i++)
#pragma unroll
                for (int j = 0; j < TC; j++)
                    acc[i][j] = fmaf(a[i], b[j], acc[i][j]);
        }
    }
#pragma unroll
    for (int i = 0; i < TR; i++) {
        int r = n0 + rg*TR + i;
        float rs = HASBASE ? (1.f / (float)max(cnt[r], 1)) : 0.f;
#pragma unroll
        for (int j = 0; j < TC; j++) {
            int col = cg*TC + j;
            float v = acc[i][j] + bsh[col];
            if (HASBASE) v += rs * base[(size_t)r*J + col];
            if (RELU) v = fmaxf(v, 0.f);
            C[(size_t)r*J + col] = v;
            if (DUAL) C2[(size_t)r*J + col] = v;
        }
    }
}

__global__ void counts(const int* __restrict__ ei, const int* __restrict__ batch,
                       int* __restrict__ cntd, int* __restrict__ cnts, int* __restrict__ bcnt)
{
    int e = blockIdx.x * 256 + threadIdx.x;
    if (e < EE) {
        atomicAdd(&cnts[ei[e]], 1);
        atomicAdd(&cntd[ei[EE + e]], 1);
    }
    if (e < NN) atomicAdd(&bcnt[batch[e]], 1);
}

__global__ void scan_src(const int* __restrict__ cnt, int* __restrict__ off, int* __restrict__ cur)
{
    __shared__ int part[1024];
    const int t = threadIdx.x;
    int c[4]; int s = 0;
#pragma unroll
    for (int i = 0; i < 4; i++) { c[i] = cnt[t*4 + i]; s += c[i]; }
    part[t] = s;
    __syncthreads();
    for (int st = 1; st < 1024; st <<= 1) {
        int v = (t >= st) ? part[t - st] : 0;
        __syncthreads();
        part[t] += v;
        __syncthreads();
    }
    int base = (t > 0) ? part[t - 1] : 0;
#pragma unroll
    for (int i = 0; i < 4; i++) { off[t*4 + i] = base; cur[t*4 + i] = base; base += c[i]; }
    if (t == 1023) off[NN] = part[1023];
}

__global__ void scatter_edges(const int* __restrict__ ei, int* __restrict__ cur,
                              int* __restrict__ order)
{
    int e = blockIdx.x * 256 + threadIdx.x;
    if (e < EE) {
        int p = atomicAdd(&cur[ei[e]], 1);
        order[p] = e;
    }
}

__global__ void edge_msg_csr(const float* __restrict__ hidden, const float* __restrict__ z,
                             const int* __restrict__ ei, const int* __restrict__ off,
                             const int* __restrict__ order, float* __restrict__ agg)
{
    const int s = blockIdx.x;
    const int beg = off[s], end = off[s + 1];
    if (beg == end) return;
    __shared__ float Zs[NC];
    __shared__ float hsh[8][64];
    const int t = threadIdx.x;
    const float4* zsrc = (const float4*)(z + (size_t)s * ZWP);
    for (int i = t; i < NC/4; i += 256) ((float4*)Zs)[i] = zsrc[i];
    __syncthreads();
    const int w = t >> 5, lane = t & 31;
    for (int idx = beg + w; idx < end; idx += 8) {
        const int e = order[idx];
        hsh[w][lane]      = hidden[(size_t)e*64 + lane];
        hsh[w][lane + 32] = hidden[(size_t)e*64 + 32 + lane];
        __syncwarp();
        float ax = Zs[4096 + 2*lane], ay = Zs[4096 + 2*lane + 1];
#pragma unroll 8
        for (int k = 0; k < 64; k++) {
            float h = hsh[w][k];
            float2 v = ((const float2*)Zs)[k*32 + lane];
            ax = fmaf(h, v.x, ax);
            ay = fmaf(h, v.y, ay);
        }
        const int dst = ei[EE + e];
        atomicAdd(&agg[(size_t)dst*64 + 2*lane],     ax);
        atomicAdd(&agg[(size_t)dst*64 + 2*lane + 1], ay);
        __syncwarp();
    }
}

__global__ void dgn_softmax(const float* __restrict__ m, const float* __restrict__ lin,
                            float* __restrict__ s)
{
    __shared__ float msh[64][65];
    __shared__ float lsh[64*GG];
    const int t = threadIdx.x;
    const int n0 = blockIdx.x * 64;
    for (int r = 0; r < 64; r++) msh[r][t] = m[(size_t)(n0 + r)*64 + t];
    for (int i = t; i < 64*GG; i += 64) lsh[i] = lin[i];
    __syncthreads();
    float logit[GG];
#pragma unroll
    for (int g = 0; g < GG; g++) logit[g] = 0.f;
    for (int k = 0; k < 64; k++) {
        float mv = msh[t][k];
#pragma unroll
        for (int g = 0; g < GG; g++) logit[g] = fmaf(mv, lsh[k*GG + g], logit[g]);
    }
    float mx = logit[0];
#pragma unroll
    for (int g = 1; g < GG; g++) mx = fmaxf(mx, logit[g]);
    float sum = 0.f;
#pragma unroll
    for (int g = 0; g < GG; g++) { logit[g] = expf(logit[g] - mx); sum += logit[g]; }
    float inv = 1.f / sum;
#pragma unroll
    for (int g = 0; g < GG; g++) s[(size_t)(n0 + t)*GG + g] = logit[g] * inv;
}

__global__ void dgn_stats(const float* __restrict__ m, const float* __restrict__ s,
                          const float* __restrict__ gamma, const float* __restrict__ beta,
                          float* __restrict__ inv, float* __restrict__ shift)
{
    const int c = blockIdx.x;
    const int g = c / 64, dd = c % 64;
    float sum = 0.f, sq = 0.f;
    for (int n = threadIdx.x; n < NN; n += 256) {
        float t = s[(size_t)n*GG + g] * m[(size_t)n*64 + dd];
        sum += t; sq = fmaf(t, t, sq);
    }
    __shared__ float rs[256], rq[256];
    rs[threadIdx.x] = sum; rq[threadIdx.x] = sq;
    __syncthreads();
    for (int st = 128; st > 0; st >>= 1) {
        if (threadIdx.x < st) { rs[threadIdx.x] += rs[threadIdx.x + st]; rq[threadIdx.x] += rq[threadIdx.x + st]; }
        __syncthreads();
    }
    if (threadIdx.x == 0) {
        float mu = rs[0] / (float)NN;
        float var = rq[0] / (float)NN - mu*mu;
        float iv = gamma[c] * rsqrtf(var + 1e-5f);
        inv[c] = iv;
        shift[c] = beta[c] - mu * iv;
    }
}

__global__ void dgn_apply(const float* __restrict__ m, const float* __restrict__ s,
                          const float* __restrict__ inv, const float* __restrict__ shift,
                          float* __restrict__ m2)
{
    __shared__ float ssh[64*GG];
    __shared__ float ish[GG*64];
    __shared__ float csh[64];
    const int t = threadIdx.x;
    const int n0 = blockIdx.x * 64;
    for (int i = t; i < 64*GG; i += 256) ssh[i] = s[(size_t)n0*GG + i];
    for (int i = t; i < GG*64; i += 256) ish[i] = inv[i];
    if (t < 64) {
        float cs = 0.f;
#pragma unroll
        for (int g = 0; g < GG; g++) cs += shift[g*64 + t];
        csh[t] = cs;
    }
    __syncthreads();
    for (int idx = t; idx < 4096; idx += 256) {
        int nl = idx / 64, dd = idx % 64;
        float a = 0.f;
#pragma unroll
        for (int g = 0; g < GG; g++) a = fmaf(ssh[nl*GG + g], ish[g*64 + dd], a);
        float mv = m[(size_t)(n0 + nl)*64 + dd];
        float v = mv + 0.01f * fmaf(mv, a, csh[dd]);
        m2[(size_t)(n0 + nl)*64 + dd] = fmaxf(v, 0.f);
    }
}

__global__ void gru_gate(const float* __restrict__ gi, const float* __restrict__ gh,
                         float* __restrict__ h, float* __restrict__ out)
{
    int i = blockIdx.x * 256 + threadIdx.x;
    int n = i >> 6, dd = i & 63;
    const float* gin = gi + (size_t)n*192;
    const float* ghn = gh + (size_t)n*192;
    float r  = 1.f / (1.f + expf(-(gin[dd] + ghn[dd])));
    float zz = 1.f / (1.f + expf(-(gin[64+dd] + ghn[64+dd])));
    float nn = tanhf(fmaf(r, ghn[128+dd], gin[128+dd]));
    float hv = h[i];
    float hnew = fmaf(zz, hv, (1.f - zz) * nn);
    h[i] = hnew;
    out[i] = hnew + out[i];
}

__global__ void pool(const float* __restrict__ out, const int* __restrict__ batch,
                     float* __restrict__ pooled)
{
    int i = blockIdx.x * 256 + threadIdx.x;
    atomicAdd(&pooled[batch[i >> 6]*64 + (i & 63)], out[i]);
}

__global__ void head(const float* __restrict__ pooled, const int* __restrict__ bcnt,
                     const float* __restrict__ postW, const float* __restrict__ postb,
                     const float* __restrict__ outW, const float* __restrict__ outb,
                     float* __restrict__ y)
{
    const int b = blockIdx.x;
    const int j = threadIdx.x;
    __shared__ float pr[64];
    __shared__ float red[64];
    float invv = 1.f / (float)max(bcnt[b], 1);
    pr[j] = pooled[b*64 + j] * invv;
    __syncthreads();
    float acc = postb[j];
    for (int k = 0; k < 64; k++) acc = fmaf(pr[k], postW[k*64 + j], acc);
    float pv = fmaxf(acc, 0.f) * outW[j];
    red[j] = pv;
    __syncthreads();
    for (int st = 32; st > 0; st >>= 1) {
        if (j < st) red[j] += red[j + st];
        __syncthreads();
    }
    if (j == 0) y[b] = red[0] + outb[0];
}

__global__ void tkl_kernel(const float* __restrict__ preW, const float* __restrict__ preb,
                           const float* __restrict__ postW, const float* __restrict__ postb,
                           const float* __restrict__ outW, const float* __restrict__ outb,
                           float* __restrict__ dst)
{
    const double logc = log(0.15 * sqrt(2.0 * 3.14159265358979323846));
    double acc = 0.0;
    const int tid = threadIdx.x;
    const float* arrs[6] = {preW, preb, postW, postb, outW, outb};
    const int lens[6] = {128*64, 64, 64*64, 64, 64, 1};
    for (int a = 0; a < 6; a++)
        for (int i = tid; i < lens[a]; i += 256) {
            double v = (double)arrs[a][i] / 0.15;
            acc += 0.5 * v * v + logc;
        }
    __shared__ double red[256];
    red[tid] = acc;
    __syncthreads();
    for (int st = 128; st > 0; st >>= 1) {
        if (tid < st) red[tid] += red[tid + st];
        __syncthreads();
    }
    if (tid == 0) dst[0] = (float)red[0];
}

extern "C" void kernel_launch(void* const* d_in, const int* in_sizes, int n_in,
                              void* d_out, int out_size)
{
    const float* x         = (const float*)d_in[0];
    const float* edge_attr = (const float*)d_in[1];
    const float* pre_W     = (const float*)d_in[2];
    const float* pre_b     = (const float*)d_in[3];
    const float* edge_w1   = (const float*)d_in[4];
    const float* edge_b1   = (const float*)d_in[5];
    const float* edge_w2   = (const float*)d_in[6];
    const float* edge_b2   = (const float*)d_in[7];
    const float* root_w    = (const float*)d_in[8];
    const float* root_b    = (const float*)d_in[9];
    const float* gru_wih   = (const float*)d_in[10];
    const float* gru_whh   = (const float*)d_in[11];
    const float* gru_bih   = (const float*)d_in[12];
    const float* gru_bhh   = (const float*)d_in[13];
    const float* gn_lin    = (const float*)d_in[14];
    const float* gn_gamma  = (const float*)d_in[15];
    const float* gn_beta   = (const float*)d_in[16];
    const float* post_W    = (const float*)d_in[17];
    const float* post_b    = (const float*)d_in[18];
    const float* out_W     = (const float*)d_in[19];
    const float* out_b     = (const float*)d_in[20];
    const int*   ei        = (const int*)d_in[21];
    const int*   batch     = (const int*)d_in[22];
    float* y = (float*)d_out;

    float *p_out, *p_h, *p_hidden, *p_z, *p_agg, *p_m, *p_m2, *p_s, *p_inv, *p_shift,
          *p_gi, *p_gh, *p_pooled;
    int *p_cntd, *p_cnts, *p_bcnt, *p_soff, *p_cur, *p_order;
    cudaGetSymbolAddress((void**)&p_out, g_out);
    cudaGetSymbolAddress((void**)&p_h, g_h);
    cudaGetSymbolAddress((void**)&p_hidden, g_hidden);
    cudaGetSymbolAddress((void**)&p_z, g_z);
    cudaGetSymbolAddress((void**)&p_agg, g_agg);
    cudaGetSymbolAddress((void**)&p_m, g_m);
    cudaGetSymbolAddress((void**)&p_m2, g_m2);
    cudaGetSymbolAddress((void**)&p_s, g_s);
    cudaGetSymbolAddress((void**)&p_inv, g_inv);
    cudaGetSymbolAddress((void**)&p_shift, g_shift);
    cudaGetSymbolAddress((void**)&p_gi, g_gi);
    cudaGetSymbolAddress((void**)&p_gh, g_gh);
    cudaGetSymbolAddress((void**)&p_pooled, g_pooled);
    cudaGetSymbolAddress((void**)&p_cntd, g_cntd);
    cudaGetSymbolAddress((void**)&p_cnts, g_cnts);
    cudaGetSymbolAddress((void**)&p_bcnt, g_bcnt);
    cudaGetSymbolAddress((void**)&p_soff, g_soff);
    cudaGetSymbolAddress((void**)&p_cur, g_cur);
    cudaGetSymbolAddress((void**)&p_order, g_order);

    cudaMemsetAsync(p_cntd, 0, NN * sizeof(int));
    cudaMemsetAsync(p_cnts, 0, NN * sizeof(int));
    cudaMemsetAsync(p_bcnt, 0, BB * sizeof(int));
    cudaMemsetAsync(p_pooled, 0, BB * 64 * sizeof(float));

    if (out_size >= 65)
        tkl_kernel<<<1, 256>>>(pre_W, pre_b, post_W, post_b, out_W, out_b, y + 64);

    counts<<<EE/256, 256>>>(ei, batch, p_cntd, p_cnts, p_bcnt);
    scan_src<<<1, 1024>>>(p_cnts, p_soff, p_cur);
    scatter_edges<<<EE/256, 256>>>(ei, p_cur, p_order);

    // pre FC + relu; writes both out and h
    gemm_small<128,64,4,false,true,false,true><<<NN/64, 256>>>(x, pre_W, pre_b, nullptr, nullptr, p_out, p_h);

    for (int i = 0; i < 3; i++) {
        const float* w1 = edge_w1 + (size_t)i*64*64;
        const float* b1 = edge_b1 + (size_t)i*64;
        const float* w2 = edge_w2 + (size_t)i*64*4096;
        const float* b2 = edge_b2 + (size_t)i*4096;

        gemm_small<64,64,4,false,true,false,false><<<EE/64, 256>>>(edge_attr, w1, b1, nullptr, nullptr, p_hidden, nullptr);

        zgemm<<<dim3(NN/64, 65), 128>>>(p_out, w2, b2, p_z);

        cudaMemsetAsync(p_agg, 0, NN*64*sizeof(float));
        edge_msg_csr<<<NN, 256>>>(p_hidden, p_z, ei, p_soff, p_order, p_agg);

        gemm_small<64,64,4,false,false,true,false><<<NN/64, 256>>>(p_out, root_w + (size_t)i*4096,
            root_b + (size_t)i*64, p_agg, p_cntd, p_m, nullptr);

        dgn_softmax<<<NN/64, 64>>>(p_m, gn_lin + (size_t)i*64*GG, p_s);
        dgn_stats<<<GG*64, 256>>>(p_m, p_s, gn_gamma + (size_t)i*GG*64, gn_beta + (size_t)i*GG*64, p_inv, p_shift);
        dgn_apply<<<NN/64, 256>>>(p_m, p_s, p_inv, p_shift, p_m2);

        gemm_small<64,192,12,true,false,false,false><<<NN/64, 256>>>(p_m2, gru_wih + (size_t)i*192*64,
            gru_bih + (size_t)i*192, nullptr, nullptr, p_gi, nullptr);
        gemm_small<64,192,12,true,false,false,false><<<NN/64, 256>>>(p_h, gru_whh + (size_t)i*192*64,
            gru_bhh + (size_t)i*192, nullptr, nullptr, p_gh, nullptr);
        gru_gate<<<NN*64/256, 256>>>(p_gi, p_gh, p_h, p_out);
    }

    pool<<<NN*64/256, 256>>>(p_out, batch, p_pooled);
    head<<<BB, 64>>>(p_pooled, p_bcnt, post_W, post_b, out_W, out_b, y);
}

// round 10
// speedup vs baseline: 1.5797x; 1.0860x over previous
#include <cuda_runtime.h>
#include <cuda_bf16.h>
#include <math.h>
#include <stdint.h>

#define NN 4096
#define EE 32768
#define BB 64
#define GG 10
#define ZWP 4224      // padded z row stride (66*64); real cols = 4160, bias slice at 4096
#define NC 4160

__device__ float g_out[NN*64];
__device__ float g_h[NN*64];
__device__ float g_hidden[(size_t)3*EE*64];
__device__ float g_z[(size_t)NN*ZWP];
__device__ float g_agg[NN*64];
__device__ float g_m[NN*64];
__device__ float g_m2[NN*64];
__device__ float g_s[NN*GG];
__device__ float g_inv[GG*64];
__device__ float g_shift[GG*64];
__device__ float g_gi[NN*192];
__device__ float g_pooled[BB*64];
__device__ float g_psum[1280];      // [0:640) sum, [640:1280) sumsq
__device__ int   g_cntd[NN];
__device__ int   g_cnts[NN];
__device__ int   g_bcnt[BB];
__device__ int   g_soff[NN+1];
__device__ int   g_cur[NN];
__device__ int   g_order[EE];

// ---------- packed f32x2 helpers ----------
__device__ __forceinline__ void fma2(uint64_t& d, uint64_t a, uint64_t b) {
    asm("fma.rn.f32x2 %0, %1, %2, %3;" : "=l"(d) : "l"(a), "l"(b), "l"(d));
}
__device__ __forceinline__ uint64_t splat2(float v) {
    uint64_t r;
    asm("mov.b64 %0, {%1, %1};" : "=l"(r) : "f"(v));
    return r;
}
__device__ __forceinline__ float2 u2f(uint64_t v) {
    float2 r;
    asm("mov.b64 {%0, %1}, %2;" : "=f"(r.x), "=f"(r.y) : "l"(v));
    return r;
}
__device__ __forceinline__ float sigm(float x) { return 1.f / (1.f + expf(-x)); }

// ---------- z GEMM: z[n, slice, :] = out[n,:] @ w2[slice] (slice 64 = b2), f32x2 inner ----------
__global__ void zgemm(const float* __restrict__ out, const float* __restrict__ w2,
                      const float* __restrict__ b2, float* __restrict__ z)
{
    __shared__ float As[64][68];
    __shared__ float Bs[64][64];
    const int tid = threadIdx.x;     // 128
    const int n0 = blockIdx.x * 64;
    const int d  = blockIdx.y;
    const float* Bsrc = (d < 64) ? (w2 + d * 4096) : b2;
    for (int idx = tid; idx < 4096; idx += 128) {
        As[idx % 64][idx / 64] = out[(size_t)(n0 + idx / 64) * 64 + (idx % 64)];
        Bs[idx / 64][idx % 64] = Bsrc[idx];
    }
    __syncthreads();
    const int rg = tid >> 4, cg = tid & 15;
    uint64_t acc[4][4];
#pragma unroll
    for (int p = 0; p < 4; p++)
#pragma unroll
        for (int j = 0; j < 4; j++) acc[p][j] = 0ull;
#pragma unroll 8
    for (int k = 0; k < 64; k++) {
        uint64_t a[4];
#pragma unroll
        for (int p = 0; p < 4; p++)
            a[p] = *(const uint64_t*)&As[k][rg*8 + 2*p];
#pragma unroll
        for (int j = 0; j < 4; j++) {
            uint64_t bs = splat2(Bs[k][cg*4 + j]);
#pragma unroll
            for (int p = 0; p < 4; p++) fma2(acc[p][j], a[p], bs);
        }
    }
#pragma unroll
    for (int p = 0; p < 4; p++) {
        float2 v0 = u2f(acc[p][0]), v1 = u2f(acc[p][1]), v2 = u2f(acc[p][2]), v3 = u2f(acc[p][3]);
        size_t r0 = (size_t)(n0 + rg*8 + 2*p) * ZWP + d*64 + cg*4;
        *(float4*)&z[r0]       = make_float4(v0.x, v1.x, v2.x, v3.x);
        *(float4*)&z[r0 + ZWP] = make_float4(v0.y, v1.y, v2.y, v3.y);
    }
}

// ---------- generic small GEMM (+pre DUAL, +GRU gate fuse, +3-layer batch) ----------
template<int K, int J, int TC, bool BT, bool RELU, bool HASBASE, bool DUAL, bool GRUF, bool B3>
__global__ void gemm_small(const float* __restrict__ A, const float* __restrict__ B,
                           const float* __restrict__ bias,
                           const float* __restrict__ base, const int* __restrict__ cnt,
                           float* __restrict__ C, float* __restrict__ C2)
{
    constexpr int KC = 32;
    constexpr int CG = J / TC;
    constexpr int RG = 256 / CG;
    constexpr int TR = 64 / RG;
    static_assert(RG * CG == 256, "");
    if (B3) {
        B    += blockIdx.y * K * J;
        bias += blockIdx.y * J;
        C    += (size_t)blockIdx.y * gridDim.x * 64 * J;
    }
    __shared__ float As[KC][68];
    __shared__ float Bs[KC][J];
    __shared__ float bsh[J];
    const int tid = threadIdx.x;
    const int n0 = blockIdx.x * 64;
    const int rg = tid / CG, cg = tid % CG;
    float acc[TR][TC];
#pragma unroll
    for (int i = 0; i < TR; i++)
#pragma unroll
        for (int j = 0; j < TC; j++) acc[i][j] = 0.f;
    for (int j = tid; j < J; j += 256) bsh[j] = bias[j];

    for (int kc = 0; kc < K; kc += KC) {
        __syncthreads();
        for (int idx = tid; idx < 64*KC; idx += 256) {
            int k = idx % KC, r = idx / KC;
            As[k][r] = A[(size_t)(n0 + r) * K + kc + k];
        }
        if (!BT) {
            for (int idx = tid; idx < KC*J; idx += 256) {
                int k = idx / J, j = idx % J;
                Bs[k][j] = B[(kc + k) * J + j];
            }
        } else {
            for (int idx = tid; idx < KC*J; idx += 256) {
                int j = idx / KC, k = idx % KC;
                Bs[k][j] = B[j * K + kc + k];
            }
        }
        __syncthreads();
#pragma unroll 8
        for (int k = 0; k < KC; k++) {
            float a[TR], b[TC];
#pragma unroll
            for (int i = 0; i < TR; i++) a[i] = As[k][rg*TR + i];
#pragma unroll
            for (int j = 0; j < TC; j++) {
                int col = GRUF ? ((j >> 2)*64 + cg*4 + (j & 3)) : (cg*TC + j);
                b[j] = Bs[k][col];
            }
#pragma unroll
            for (int i = 0; i < TR; i++)
#pragma unroll
                for (int j = 0; j < TC; j++)
                    acc[i][j] = fmaf(a[i], b[j], acc[i][j]);
        }
    }
    if (GRUF) {
        // acc holds gh; base = gi; C = h (in/out); C2 = out (in/out)
#pragma unroll
        for (int i = 0; i < TR; i++) {
            int r = n0 + rg*TR + i;
            const float* gin = base + (size_t)r*192;
#pragma unroll
            for (int q = 0; q < 4; q++) {
                int c = cg*4 + q;
                float ghr = acc[i][q]     + bsh[c];
                float ghz = acc[i][4 + q] + bsh[64 + c];
                float ghn = acc[i][8 + q] + bsh[128 + c];
                float rg_ = sigm(gin[c] + ghr);
                float zg  = sigm(gin[64 + c] + ghz);
                float ng  = tanhf(fmaf(rg_, ghn, gin[128 + c]));
                float ho  = C[(size_t)r*64 + c];
                float hn  = fmaf(zg, ho, (1.f - zg) * ng);
                C[(size_t)r*64 + c]  = hn;
                C2[(size_t)r*64 + c] += hn;
            }
        }
    } else {
#pragma unroll
        for (int i = 0; i < TR; i++) {
            int r = n0 + rg*TR + i;
            float rs = HASBASE ? (1.f / (float)max(cnt[r], 1)) : 0.f;
#pragma unroll
            for (int j = 0; j < TC; j++) {
                int col = cg*TC + j;
                float v = acc[i][j] + bsh[col];
                if (HASBASE) v += rs * base[(size_t)r*J + col];
                if (RELU) v = fmaxf(v, 0.f);
                C[(size_t)r*J + col] = v;
                if (DUAL) C2[(size_t)r*J + col] = v;
            }
        }
    }
}

// ---------- CSR build ----------
__global__ void counts(const int* __restrict__ ei, const int* __restrict__ batch,
                       int* __restrict__ cntd, int* __restrict__ cnts, int* __restrict__ bcnt)
{
    int e = blockIdx.x * 256 + threadIdx.x;
    if (e < EE) {
        atomicAdd(&cnts[ei[e]], 1);
        atomicAdd(&cntd[ei[EE + e]], 1);
    }
    if (e < NN) atomicAdd(&bcnt[batch[e]], 1);
}

__global__ void scan_src(const int* __restrict__ cnt, int* __restrict__ off, int* __restrict__ cur)
{
    __shared__ int part[1024];
    const int t = threadIdx.x;
    int c[4]; int s = 0;
#pragma unroll
    for (int i = 0; i < 4; i++) { c[i] = cnt[t*4 + i]; s += c[i]; }
    part[t] = s;
    __syncthreads();
    for (int st = 1; st < 1024; st <<= 1) {
        int v = (t >= st) ? part[t - st] : 0;
        __syncthreads();
        part[t] += v;
        __syncthreads();
    }
    int base = (t > 0) ? part[t - 1] : 0;
#pragma unroll
    for (int i = 0; i < 4; i++) { off[t*4 + i] = base; cur[t*4 + i] = base; base += c[i]; }
    if (t == 1023) off[NN] = part[1023];
}

__global__ void scatter_edges(const int* __restrict__ ei, int* __restrict__ cur,
                              int* __restrict__ order)
{
    int e = blockIdx.x * 256 + threadIdx.x;
    if (e < EE) {
        int p = atomicAdd(&cur[ei[e]], 1);
        order[p] = e;
    }
}

// ---------- edge messages (f32x2 inner) ----------
__global__ void edge_msg_csr(const float* __restrict__ hidden, const float* __restrict__ z,
                             const int* __restrict__ ei, const int* __restrict__ off,
                             const int* __restrict__ order, float* __restrict__ agg)
{
    const int s = blockIdx.x;
    const int beg = off[s], end = off[s + 1];
    if (beg == end) return;
    __shared__ float Zs[NC];
    __shared__ float hsh[8][64];
    const int t = threadIdx.x;
    const float4* zsrc = (const float4*)(z + (size_t)s * ZWP);
    for (int i = t; i < NC/4; i += 256) ((float4*)Zs)[i] = zsrc[i];
    __syncthreads();
    const int w = t >> 5, lane = t & 31;
    for (int idx = beg + w; idx < end; idx += 8) {
        const int e = order[idx];
        hsh[w][lane]      = hidden[(size_t)e*64 + lane];
        hsh[w][lane + 32] = hidden[(size_t)e*64 + 32 + lane];
        __syncwarp();
        uint64_t acc = *(const uint64_t*)&Zs[4096 + 2*lane];   // bias slice
#pragma unroll 8
        for (int k = 0; k < 64; k++)
            fma2(acc, ((const uint64_t*)Zs)[k*32 + lane], splat2(hsh[w][k]));
        float2 v = u2f(acc);
        const int dst = ei[EE + e];
        atomicAdd(&agg[(size_t)dst*64 + 2*lane],     v.x);
        atomicAdd(&agg[(size_t)dst*64 + 2*lane + 1], v.y);
        __syncwarp();
    }
}

// ---------- fused: m = agg/cnt + out@root_w + root_b ; s = softmax(m@lin) ; stats partials ----------
__global__ void root_dgn(const float* __restrict__ out, const float* __restrict__ rw,
                         const float* __restrict__ rb, const float* __restrict__ agg,
                         const int* __restrict__ cntd, const float* __restrict__ lin,
                         float* __restrict__ m, float* __restrict__ s, float* __restrict__ psum)
{
    __shared__ float As[64][65];
    __shared__ float Bs[64][64];
    __shared__ float msh[64][65];
    __shared__ float ssh[64][GG];
    __shared__ float lsh[64*GG];
    const int tid = threadIdx.x;   // 256
    const int n0 = blockIdx.x * 64;
    for (int idx = tid; idx < 4096; idx += 256) {
        As[idx % 64][idx / 64] = out[(size_t)(n0 + idx / 64) * 64 + (idx % 64)];
        Bs[idx / 64][idx % 64] = rw[idx];
    }
    for (int i = tid; i < 64*GG; i += 256) lsh[i] = lin[i];
    __syncthreads();
    const int rg = tid >> 4, cg = tid & 15;
    float acc[4][4];
#pragma unroll
    for (int i = 0; i < 4; i++)
#pragma unroll
        for (int j = 0; j < 4; j++) acc[i][j] = 0.f;
#pragma unroll 8
    for (int k = 0; k < 64; k++) {
        float a[4], b[4];
#pragma unroll
        for (int i = 0; i < 4; i++) a[i] = As[k][rg*4 + i];
#pragma unroll
        for (int j = 0; j < 4; j++) b[j] = Bs[k][cg*4 + j];
#pragma unroll
        for (int i = 0; i < 4; i++)
#pragma unroll
            for (int j = 0; j < 4; j++)
                acc[i][j] = fmaf(a[i], b[j], acc[i][j]);
    }
#pragma unroll
    for (int i = 0; i < 4; i++) {
        int lr = rg*4 + i, r = n0 + lr;
        float rs = 1.f / (float)max(cntd[r], 1);
#pragma unroll
        for (int j = 0; j < 4; j++) {
            int col = cg*4 + j;
            float v = acc[i][j] + rb[col] + rs * agg[(size_t)r*64 + col];
            msh[lr][col] = v;
            m[(size_t)r*64 + col] = v;
        }
    }
    __syncthreads();
    // softmax: one thread per row (first 64 threads)
    if (tid < 64) {
        float logit[GG];
#pragma unroll
        for (int g = 0; g < GG; g++) logit[g] = 0.f;
        for (int k = 0; k < 64; k++) {
            float mv = msh[tid][k];
#pragma unroll
            for (int g = 0; g < GG; g++) logit[g] = fmaf(mv, lsh[k*GG + g], logit[g]);
        }
        float mx = logit[0];
#pragma unroll
        for (int g = 1; g < GG; g++) mx = fmaxf(mx, logit[g]);
        float sum = 0.f;
#pragma unroll
        for (int g = 0; g < GG; g++) { logit[g] = expf(logit[g] - mx); sum += logit[g]; }
        float inv = 1.f / sum;
#pragma unroll
        for (int g = 0; g < GG; g++) {
            float sv = logit[g] * inv;
            ssh[tid][g] = sv;
            s[(size_t)(n0 + tid)*GG + g] = sv;
        }
    }
    __syncthreads();
    // stats partials: channel c = g*64+d
    for (int c = tid; c < 640; c += 256) {
        int g = c >> 6, dd = c & 63;
        float sum = 0.f, sq = 0.f;
#pragma unroll 8
        for (int r = 0; r < 64; r++) {
            float t = ssh[r][g] * msh[r][dd];
            sum += t;
            sq = fmaf(t, t, sq);
        }
        atomicAdd(&psum[c], sum);
        atomicAdd(&psum[640 + c], sq);
    }
}

__global__ void dgn_fin(const float* __restrict__ gamma, const float* __restrict__ beta,
                        float* __restrict__ psum, float* __restrict__ inv, float* __restrict__ shift)
{
    int c = threadIdx.x;   // 640
    float mu = psum[c] / (float)NN;
    float var = psum[640 + c] / (float)NN - mu*mu;
    float iv = gamma[c] * rsqrtf(var + 1e-5f);
    inv[c] = iv;
    shift[c] = beta[c] - mu * iv;
    psum[c] = 0.f;
    psum[640 + c] = 0.f;
}

__global__ void dgn_apply(const float* __restrict__ m, const float* __restrict__ s,
                          const float* __restrict__ inv, const float* __restrict__ shift,
                          float* __restrict__ m2)
{
    __shared__ float ssh[64*GG];
    __shared__ float ish[GG*64];
    __shared__ float csh[64];
    const int t = threadIdx.x;
    const int n0 = blockIdx.x * 64;
    for (int i = t; i < 64*GG; i += 256) ssh[i] = s[(size_t)n0*GG + i];
    for (int i = t; i < GG*64; i += 256) ish[i] = inv[i];
    if (t < 64) {
        float cs = 0.f;
#pragma unroll
        for (int g = 0; g < GG; g++) cs += shift[g*64 + t];
        csh[t] = cs;
    }
    __syncthreads();
    for (int idx = t; idx < 4096; idx += 256) {
        int nl = idx / 64, dd = idx % 64;
        float a = 0.f;
#pragma unroll
        for (int g = 0; g < GG; g++) a = fmaf(ssh[nl*GG + g], ish[g*64 + dd], a);
        float mv = m[(size_t)(n0 + nl)*64 + dd];
        float v = mv + 0.01f * fmaf(mv, a, csh[dd]);
        m2[(size_t)(n0 + nl)*64 + dd] = fmaxf(v, 0.f);
    }
}

__global__ void pool(const float* __restrict__ out, const int* __restrict__ batch,
                     float* __restrict__ pooled)
{
    int i = blockIdx.x * 256 + threadIdx.x;
    atomicAdd(&pooled[batch[i >> 6]*64 + (i & 63)], out[i]);
}

__global__ void head(const float* __restrict__ pooled, const int* __restrict__ bcnt,
                     const float* __restrict__ postW, const float* __restrict__ postb,
                     const float* __restrict__ outW, const float* __restrict__ outb,
                     float* __restrict__ y)
{
    const int b = blockIdx.x;
    const int j = threadIdx.x;
    __shared__ float pr[64];
    __shared__ float red[64];
    float invv = 1.f / (float)max(bcnt[b], 1);
    pr[j] = pooled[b*64 + j] * invv;
    __syncthreads();
    float acc = postb[j];
    for (int k = 0; k < 64; k++) acc = fmaf(pr[k], postW[k*64 + j], acc);
    float pv = fmaxf(acc, 0.f) * outW[j];
    red[j] = pv;
    __syncthreads();
    for (int st = 32; st > 0; st >>= 1) {
        if (j < st) red[j] += red[j + st];
        __syncthreads();
    }
    if (j == 0) y[b] = red[0] + outb[0];
}

__global__ void tkl_kernel(const float* __restrict__ preW, const float* __restrict__ preb,
                           const float* __restrict__ postW, const float* __restrict__ postb,
                           const float* __restrict__ outW, const float* __restrict__ outb,
                           float* __restrict__ dst)
{
    const double logc = log(0.15 * sqrt(2.0 * 3.14159265358979323846));
    double acc = 0.0;
    const int tid = threadIdx.x;
    const float* arrs[6] = {preW, preb, postW, postb, outW, outb};
    const int lens[6] = {128*64, 64, 64*64, 64, 64, 1};
    for (int a = 0; a < 6; a++)
        for (int i = tid; i < lens[a]; i += 256) {
            double v = (double)arrs[a][i] / 0.15;
            acc += 0.5 * v * v + logc;
        }
    __shared__ double red[256];
    red[tid] = acc;
    __syncthreads();
    for (int st = 128; st > 0; st >>= 1) {
        if (tid < st) red[tid] += red[tid + st];
        __syncthreads();
    }
    if (tid == 0) dst[0] = (float)red[0];
}

extern "C" void kernel_launch(void* const* d_in, const int* in_sizes, int n_in,
                              void* d_out, int out_size)
{
    const float* x         = (const float*)d_in[0];
    const float* edge_attr = (const float*)d_in[1];
    const float* pre_W     = (const float*)d_in[2];
    const float* pre_b     = (const float*)d_in[3];
    const float* edge_w1   = (const float*)d_in[4];
    const float* edge_b1   = (const float*)d_in[5];
    const float* edge_w2   = (const float*)d_in[6];
    const float* edge_b2   = (const float*)d_in[7];
    const float* root_w    = (const float*)d_in[8];
    const float* root_b    = (const float*)d_in[9];
    const float* gru_wih   = (const float*)d_in[10];
    const float* gru_whh   = (const float*)d_in[11];
    const float* gru_bih   = (const float*)d_in[12];
    const float* gru_bhh   = (const float*)d_in[13];
    const float* gn_lin    = (const float*)d_in[14];
    const float* gn_gamma  = (const float*)d_in[15];
    const float* gn_beta   = (const float*)d_in[16];
    const float* post_W    = (const float*)d_in[17];
    const float* post_b    = (const float*)d_in[18];
    const float* out_W     = (const float*)d_in[19];
    const float* out_b     = (const float*)d_in[20];
    const int*   ei        = (const int*)d_in[21];
    const int*   batch     = (const int*)d_in[22];
    float* y = (float*)d_out;

    float *p_out, *p_h, *p_hidden, *p_z, *p_agg, *p_m, *p_m2, *p_s, *p_inv, *p_shift,
          *p_gi, *p_pooled, *p_psum;
    int *p_cntd, *p_cnts, *p_bcnt, *p_soff, *p_cur, *p_order;
    cudaGetSymbolAddress((void**)&p_out, g_out);
    cudaGetSymbolAddress((void**)&p_h, g_h);
    cudaGetSymbolAddress((void**)&p_hidden, g_hidden);
    cudaGetSymbolAddress((void**)&p_z, g_z);
    cudaGetSymbolAddress((void**)&p_agg, g_agg);
    cudaGetSymbolAddress((void**)&p_m, g_m);
    cudaGetSymbolAddress((void**)&p_m2, g_m2);
    cudaGetSymbolAddress((void**)&p_s, g_s);
    cudaGetSymbolAddress((void**)&p_inv, g_inv);
    cudaGetSymbolAddress((void**)&p_shift, g_shift);
    cudaGetSymbolAddress((void**)&p_gi, g_gi);
    cudaGetSymbolAddress((void**)&p_pooled, g_pooled);
    cudaGetSymbolAddress((void**)&p_psum, g_psum);
    cudaGetSymbolAddress((void**)&p_cntd, g_cntd);
    cudaGetSymbolAddress((void**)&p_cnts, g_cnts);
    cudaGetSymbolAddress((void**)&p_bcnt, g_bcnt);
    cudaGetSymbolAddress((void**)&p_soff, g_soff);
    cudaGetSymbolAddress((void**)&p_cur, g_cur);
    cudaGetSymbolAddress((void**)&p_order, g_order);

    cudaMemsetAsync(p_cntd, 0, NN * sizeof(int));
    cudaMemsetAsync(p_cnts, 0, NN * sizeof(int));
    cudaMemsetAsync(p_bcnt, 0, BB * sizeof(int));
    cudaMemsetAsync(p_pooled, 0, BB * 64 * sizeof(float));
    cudaMemsetAsync(p_psum, 0, 1280 * sizeof(float));

    if (out_size >= 65)
        tkl_kernel<<<1, 256>>>(pre_W, pre_b, post_W, post_b, out_W, out_b, y + 64);

    counts<<<EE/256, 256>>>(ei, batch, p_cntd, p_cnts, p_bcnt);
    scan_src<<<1, 1024>>>(p_cnts, p_soff, p_cur);
    scatter_edges<<<EE/256, 256>>>(ei, p_cur, p_order);

    // all 3 layers' hidden = relu(edge_attr @ w1 + b1) in one launch
    gemm_small<64,64,4,false,true,false,false,false,true><<<dim3(EE/64, 3), 256>>>(
        edge_attr, edge_w1, edge_b1, nullptr, nullptr, p_hidden, nullptr);

    // pre FC + relu; writes both out and h
    gemm_small<128,64,4,false,true,false,true,false,false><<<NN/64, 256>>>(
        x, pre_W, pre_b, nullptr, nullptr, p_out, p_h);

    for (int i = 0; i < 3; i++) {
        const float* w2 = edge_w2 + (size_t)i*64*4096;
        const float* b2 = edge_b2 + (size_t)i*4096;

        zgemm<<<dim3(NN/64, 65), 128>>>(p_out, w2, b2, p_z);

        cudaMemsetAsync(p_agg, 0, NN*64*sizeof(float));
        edge_msg_csr<<<NN, 256>>>(p_hidden + (size_t)i*EE*64, p_z, ei, p_soff, p_order, p_agg);

        root_dgn<<<NN/64, 256>>>(p_out, root_w + (size_t)i*4096, root_b + (size_t)i*64,
                                 p_agg, p_cntd, gn_lin + (size_t)i*64*GG, p_m, p_s, p_psum);
        dgn_fin<<<1, 640>>>(gn_gamma + (size_t)i*GG*64, gn_beta + (size_t)i*GG*64,
                            p_psum, p_inv, p_shift);
        dgn_apply<<<NN/64, 256>>>(p_m, p_s, p_inv, p_shift, p_m2);

        // gi = m2 @ wih^T + bih
        gemm_small<64,192,12,true,false,false,false,false,false><<<NN/64, 256>>>(
            p_m2, gru_wih + (size_t)i*192*64, gru_bih + (size_t)i*192,
            nullptr, nullptr, p_gi, nullptr);
        // gh GEMM + GRU gate fused: updates h and out in place
        gemm_small<64,192,12,true,false,false,false,true,false><<<NN/64, 256>>>(
            p_h, gru_whh + (size_t)i*192*64, gru_bhh + (size_t)i*192,
            p_gi, nullptr, p_h, p_out);
    }

    pool<<<NN*64/256, 256>>>(p_out, batch, p_pooled);
    head<<<BB, 64>>>(p_pooled, p_bcnt, post_W, post_b, out_W, out_b, y);
}